// round 16
// baseline (speedup 1.0000x reference)
#include <cuda_runtime.h>
#include <stdint.h>

#define D 16
#define MAX_NODES 50000

__device__ float g_sum[MAX_NODES];

__device__ __forceinline__ float dot4(float4 a, float4 b) {
    return a.x * b.x + a.y * b.y + a.z * b.z + a.w * b.w;
}
__device__ __forceinline__ float sum4(float4 a) {
    return (a.x + a.y) + (a.z + a.w);
}

// Kernel 0: zero the per-dst denominators (tiny).
__global__ void init_sum_kernel(int n_nodes) {
    int i = blockIdx.x * blockDim.x + threadIdx.x;
    if (i < n_nodes) g_sum[i] = 0.0f;
}

// Kernel 1 (fused streamer): computes the FULL logit per edge, including the
// node-key term, directly:
//   logit = q[dst]·(W_e f) + q[dst]·(b_e + f + key_n[src])
//   key_n[src][d] = feat[src][d]*rowsum(W_n[src][d,:]) + b_n[src][d]
// 16 lanes per edge. Lane d loads w_e float4s {d, d+16, d+32, d+48}
// (coalesced 1KB/edge-group, __ldcs: one-shot stream) AND the same-index
// float4s of the W_n[src] block (__ldg: ~10x reuse per node, L2-resident,
// 51MB total DRAM-unique — same as the deleted node_prep kernel read).
// Float4 j=d+16k is chunk c=d&3 of row r=4k+(d>>2); the W_n chunk
// contributes sum(chunk)*q[r]*feat[r]; w_e chunk contributes dot(chunk,
// f_chunk[c])*q[r]. All terms fold into one 16-lane xor reduce.
// exp() without max-shift (|logit| small; ratio identical); per-dst
// denominator via atomicAdd.
__global__ void __launch_bounds__(256) edge_logits_kernel(
                                   const float* __restrict__ feat,
                                   const float* __restrict__ query,
                                   const float* __restrict__ w_n,
                                   const float* __restrict__ b_n,
                                   const float* __restrict__ w_e,
                                   const float* __restrict__ b_e,
                                   const int* __restrict__ src,
                                   const int* __restrict__ dst,
                                   float* __restrict__ out,
                                   int n_edges) {
    int t = blockIdx.x * blockDim.x + threadIdx.x;
    int e = t >> 4;
    int d = t & 15;
    if (e >= n_edges) return;

    int sN = __ldg(&src[e]);
    int dN = __ldg(&dst[e]);

    int a = d >> 2;   // base row of this lane's chunks
    int c = d & 3;    // chunk index

    // feat chunk c of feat[src] (L1 broadcast within the 4-lane group).
    float4 fc = __ldg(reinterpret_cast<const float4*>(feat + (size_t)sN * D) + c);

    // One-shot w_e stream (512MB): evict-first.
    const float4* w4 = reinterpret_cast<const float4*>(w_e + (size_t)e * (D * D));
    float4 wa = __ldcs(w4 + d);
    float4 wb = __ldcs(w4 + d + 16);
    float4 wc = __ldcs(w4 + d + 32);
    float4 wd = __ldcs(w4 + d + 48);

    // q scalars for rows a, a+4, a+8, a+12 (L1/L2 hits).
    const float* q = query + (size_t)dN * D;
    float qa = __ldg(&q[a]);
    float qb = __ldg(&q[a + 4]);
    float qc = __ldg(&q[a + 8]);
    float qd = __ldg(&q[a + 12]);

    float p = dot4(wa, fc) * qa + dot4(wb, fc) * qb
            + dot4(wc, fc) * qc + dot4(wd, fc) * qd;

    // W_n[src] block, same coalesced indexing (reused across ~10 edges/node
    // -> L2 hits after first touch; keep cacheable).
    const float4* n4 = reinterpret_cast<const float4*>(w_n + (size_t)sN * (D * D));
    float4 na = __ldg(n4 + d);
    float4 nb = __ldg(n4 + d + 16);
    float4 nc = __ldg(n4 + d + 32);
    float4 nd = __ldg(n4 + d + 48);

    // feat scalars for rows a, a+4, a+8, a+12 (hit the fc lines).
    const float* fp = feat + (size_t)sN * D;
    float fa_ = __ldg(&fp[a]);
    float fb_ = __ldg(&fp[a + 4]);
    float fc_ = __ldg(&fp[a + 8]);
    float fd_ = __ldg(&fp[a + 12]);

    p += sum4(na) * (qa * fa_);
    p += sum4(nb) * (qb * fb_);
    p += sum4(nc) * (qc * fc_);
    p += sum4(nd) * (qd * fd_);

    // Linear term for component d: (b_e[d] + f[d] + b_n[src][d]) * q[d].
    float f_d = __ldg(&fp[d]);
    float lin = __ldcs(&b_e[(size_t)e * D + d]) + f_d
              + __ldg(&b_n[(size_t)sN * D + d]);
    p += lin * __ldg(&q[d]);

    #pragma unroll
    for (int off = 8; off > 0; off >>= 1)
        p += __shfl_xor_sync(0xffffffffu, p, off, 16);

    if (d == 0) {
        float ex = __expf(p);
        out[e] = ex;
        atomicAdd(&g_sum[dN], ex);
    }
}

// Kernel 2: normalize, 8 edges per thread, front-batched, reciprocal mult.
// One-shot reads via __ldcs; final writes via __stcs (never re-read).
__global__ void edge_norm_kernel(const int* __restrict__ dst,
                                 float* __restrict__ out,
                                 int n_edges) {
    int i = blockIdx.x * blockDim.x + threadIdx.x;
    int e = i * 8;
    if (e + 7 < n_edges) {
        int4   dn0 = __ldcs(reinterpret_cast<const int4*>(dst + e));
        int4   dn1 = __ldcs(reinterpret_cast<const int4*>(dst + e + 4));
        float4 o0  = __ldcs(reinterpret_cast<const float4*>(out + e));
        float4 o1  = __ldcs(reinterpret_cast<const float4*>(out + e + 4));
        float s0 = g_sum[dn0.x], s1 = g_sum[dn0.y], s2 = g_sum[dn0.z], s3 = g_sum[dn0.w];
        float s4 = g_sum[dn1.x], s5 = g_sum[dn1.y], s6 = g_sum[dn1.z], s7 = g_sum[dn1.w];
        o0.x *= __frcp_rn(s0); o0.y *= __frcp_rn(s1);
        o0.z *= __frcp_rn(s2); o0.w *= __frcp_rn(s3);
        o1.x *= __frcp_rn(s4); o1.y *= __frcp_rn(s5);
        o1.z *= __frcp_rn(s6); o1.w *= __frcp_rn(s7);
        __stcs(reinterpret_cast<float4*>(out + e), o0);
        __stcs(reinterpret_cast<float4*>(out + e + 4), o1);
    } else {
        for (; e < n_edges; e++)
            out[e] /= g_sum[__ldg(&dst[e])];
    }
}

extern "C" void kernel_launch(void* const* d_in, const int* in_sizes, int n_in,
                              void* d_out, int out_size) {
    const float* feat  = (const float*)d_in[0];   // [N,16]
    const float* w_n   = (const float*)d_in[1];   // [N,16,16]
    const float* b_n   = (const float*)d_in[2];   // [N,16]
    const float* query = (const float*)d_in[3];   // [N,16]
    const float* w_e   = (const float*)d_in[4];   // [E,16,16]
    const float* b_e   = (const float*)d_in[5];   // [E,16]
    const int*   src   = (const int*)d_in[6];     // [E]
    const int*   dst   = (const int*)d_in[7];     // [E]
    float* out = (float*)d_out;                   // [E,1]

    int n_nodes = in_sizes[0] / D;
    int n_edges = in_sizes[7];

    {
        int bs = 256;
        init_sum_kernel<<<(n_nodes + bs - 1) / bs, bs>>>(n_nodes);
    }
    {
        long long total = (long long)n_edges * D;
        int bs = 256;
        int grid = (int)((total + bs - 1) / bs);
        edge_logits_kernel<<<grid, bs>>>(feat, query, w_n, b_n, w_e, b_e,
                                         src, dst, out, n_edges);
    }
    {
        int bs = 256;
        int octs = (n_edges + 7) / 8;
        int grid = (octs + bs - 1) / bs;
        edge_norm_kernel<<<grid, bs>>>(dst, out, n_edges);
    }
}

// round 17
// speedup vs baseline: 1.1923x; 1.1923x over previous
#include <cuda_runtime.h>
#include <stdint.h>

#define D 16
#define MAX_NODES 50000

__device__ float g_key_n[MAX_NODES * D];
__device__ float g_sum[MAX_NODES];

__device__ __forceinline__ float dot4(float4 a, float4 b) {
    return a.x * b.x + a.y * b.y + a.z * b.z + a.w * b.w;
}

// Kernel 1: key_n[n,i] = feat[n,i] * rowsum(W_n[n,i,:]) + b_n[n,i]
// Direct row-per-thread (best measured variant: ~12.2us). Thread i reads
// its own W_n row as 4 sequential __ldcs float4s (warp = 32 consecutive
// rows = 2KB contiguous per round). No smem/shuffles. feat/b_n
// front-batched. g_sum zero-init embedded (free).
__global__ void __launch_bounds__(256) node_prep_kernel(
        const float* __restrict__ feat,
        const float* __restrict__ w_n,
        const float* __restrict__ b_n,
        int n_nodes) {
    int i = blockIdx.x * blockDim.x + threadIdx.x;
    int total_rows = n_nodes * D;           // 800000
    if (i >= total_rows) return;

    float f_i = __ldg(&feat[i]);
    float b_i = __ldg(&b_n[i]);

    const float4* w = reinterpret_cast<const float4*>(w_n + (size_t)i * D);
    float4 a = __ldcs(w + 0);
    float4 b = __ldcs(w + 1);
    float4 c = __ldcs(w + 2);
    float4 d = __ldcs(w + 3);

    float rs = ((a.x + a.y) + (a.z + a.w)) + ((b.x + b.y) + (b.z + b.w))
             + ((c.x + c.y) + (c.z + c.w)) + ((d.x + d.y) + (d.z + d.w));

    g_key_n[i] = f_i * rs + b_i;
    if (i < n_nodes) g_sum[i] = 0.0f;
}

// Kernel 2: the 512MB streamer, W-coalesced (measured ~78us = ~7.2TB/s,
// ~90% of HBM spec). One-shot streams (w_e, b_e) use __ldcs so they don't
// displace the L2-resident gather set (feat/query/g_key_n/src/dst, ~12MB).
// All scalar/gather loads front-batched BEFORE the FMA chain so their
// latency overlaps compute instead of being exposed at the end.
// 16 lanes per edge. Lane d loads float4 w4[d + 16k], k=0..3. Float4
// j=d+16k is chunk c=d&3 of row r=4k+(d>>2). Bilinear: lane accumulates
// q[r]*dot(w4, f_chunk[c]); single 16-lane xor reduce.
// exp() without max-shift (|logit| small; softmax ratio identical);
// per-dst denominator via atomicAdd.
__global__ void __launch_bounds__(256) edge_logits_kernel(
                                   const float* __restrict__ feat,
                                   const float* __restrict__ query,
                                   const float* __restrict__ w_e,
                                   const float* __restrict__ b_e,
                                   const int* __restrict__ src,
                                   const int* __restrict__ dst,
                                   float* __restrict__ out,
                                   int n_edges) {
    int t = blockIdx.x * blockDim.x + threadIdx.x;
    int e = t >> 4;
    int d = t & 15;
    if (e >= n_edges) return;

    int sN = __ldg(&src[e]);
    int dN = __ldg(&dst[e]);

    int a = d >> 2;   // row group
    int c = d & 3;    // chunk

    // ---- front-batch every load ----
    float4 fc = __ldg(reinterpret_cast<const float4*>(feat + (size_t)sN * D) + c);

    const float4* w4 = reinterpret_cast<const float4*>(w_e + (size_t)e * (D * D));
    float4 wa = __ldcs(w4 + d);
    float4 wb = __ldcs(w4 + d + 16);
    float4 wc = __ldcs(w4 + d + 32);
    float4 wd = __ldcs(w4 + d + 48);

    const float* q = query + (size_t)dN * D;
    float qa = __ldg(&q[a]);
    float qb = __ldg(&q[a + 4]);
    float qc = __ldg(&q[a + 8]);
    float qd = __ldg(&q[a + 12]);
    float qe = __ldg(&q[d]);

    float be  = __ldcs(&b_e[(size_t)e * D + d]);
    float f_d = __ldg(&feat[(size_t)sN * D + d]);
    float kn  = __ldg(&g_key_n[(size_t)sN * D + d]);

    // ---- compute ----
    float p = dot4(wa, fc) * qa
            + dot4(wb, fc) * qb
            + dot4(wc, fc) * qc
            + dot4(wd, fc) * qd
            + (be + f_d + kn) * qe;

    #pragma unroll
    for (int off = 8; off > 0; off >>= 1)
        p += __shfl_xor_sync(0xffffffffu, p, off, 16);

    if (d == 0) {
        float ex = __expf(p);
        out[e] = ex;
        atomicAdd(&g_sum[dN], ex);
    }
}

// Kernel 3: normalize, 8 edges per thread, front-batched, reciprocal mult.
// One-shot reads via __ldcs; final writes via __stcs (never re-read).
__global__ void edge_norm_kernel(const int* __restrict__ dst,
                                 float* __restrict__ out,
                                 int n_edges) {
    int i = blockIdx.x * blockDim.x + threadIdx.x;
    int e = i * 8;
    if (e + 7 < n_edges) {
        int4   dn0 = __ldcs(reinterpret_cast<const int4*>(dst + e));
        int4   dn1 = __ldcs(reinterpret_cast<const int4*>(dst + e + 4));
        float4 o0  = __ldcs(reinterpret_cast<const float4*>(out + e));
        float4 o1  = __ldcs(reinterpret_cast<const float4*>(out + e + 4));
        float s0 = g_sum[dn0.x], s1 = g_sum[dn0.y], s2 = g_sum[dn0.z], s3 = g_sum[dn0.w];
        float s4 = g_sum[dn1.x], s5 = g_sum[dn1.y], s6 = g_sum[dn1.z], s7 = g_sum[dn1.w];
        o0.x *= __frcp_rn(s0); o0.y *= __frcp_rn(s1);
        o0.z *= __frcp_rn(s2); o0.w *= __frcp_rn(s3);
        o1.x *= __frcp_rn(s4); o1.y *= __frcp_rn(s5);
        o1.z *= __frcp_rn(s6); o1.w *= __frcp_rn(s7);
        __stcs(reinterpret_cast<float4*>(out + e), o0);
        __stcs(reinterpret_cast<float4*>(out + e + 4), o1);
    } else {
        for (; e < n_edges; e++)
            out[e] /= g_sum[__ldg(&dst[e])];
    }
}

extern "C" void kernel_launch(void* const* d_in, const int* in_sizes, int n_in,
                              void* d_out, int out_size) {
    const float* feat  = (const float*)d_in[0];   // [N,16]
    const float* w_n   = (const float*)d_in[1];   // [N,16,16]
    const float* b_n   = (const float*)d_in[2];   // [N,16]
    const float* query = (const float*)d_in[3];   // [N,16]
    const float* w_e   = (const float*)d_in[4];   // [E,16,16]
    const float* b_e   = (const float*)d_in[5];   // [E,16]
    const int*   src   = (const int*)d_in[6];     // [E]
    const int*   dst   = (const int*)d_in[7];     // [E]
    float* out = (float*)d_out;                   // [E,1]

    int n_nodes = in_sizes[0] / D;
    int n_edges = in_sizes[7];

    {
        int total_rows = n_nodes * D;
        int bs = 256;
        node_prep_kernel<<<(total_rows + bs - 1) / bs, bs>>>(feat, w_n, b_n, n_nodes);
    }
    {
        long long total = (long long)n_edges * D;
        int bs = 256;
        int grid = (int)((total + bs - 1) / bs);
        edge_logits_kernel<<<grid, bs>>>(feat, query, w_e, b_e, src, dst, out, n_edges);
    }
    {
        int bs = 256;
        int octs = (n_edges + 7) / 8;
        int grid = (octs + bs - 1) / bs;
        edge_norm_kernel<<<grid, bs>>>(dst, out, n_edges);
    }
}